// round 2
// baseline (speedup 1.0000x reference)
#include <cuda_runtime.h>

#define T_LEN  1024
#define NSTEP  1023
#define B_SZ   8192

typedef unsigned long long ull;

// time-major input scratch
__device__ int   g_act_t[T_LEN * B_SZ];   // [t][b]
__device__ float g_rew_t[T_LEN * B_SZ];   // [t][b]

// ---------------- f32x2 packed-math helpers ----------------
__device__ __forceinline__ void ffma2(ull& d, ull a, ull b) {
    asm("fma.rn.f32x2 %0, %1, %2, %0;" : "+l"(d) : "l"(a), "l"(b));
}
__device__ __forceinline__ ull pack2(float x, float y) {
    ull r; asm("mov.b64 %0, {%1, %2};" : "=l"(r) : "f"(x), "f"(y)); return r;
}
__device__ __forceinline__ float2 unpack2(ull v) {
    float2 r; asm("mov.b64 {%0, %1}, %2;" : "=f"(r.x), "=f"(r.y) : "l"(v)); return r;
}
// accurate fast tanh: 1 - 2/(e^{2x}+1)  (~1e-6 abs err)
__device__ __forceinline__ float tanh_fast(float x) {
    float e, r;
    asm("ex2.approx.f32 %0, %1;" : "=f"(e) : "f"(x * 2.8853900817779268f));
    asm("rcp.approx.f32 %0, %1;" : "=f"(r) : "f"(e + 1.0f));
    return fmaf(-2.0f, r, 1.0f);
}

// ---------------- transpose [B][T] -> [T][B] (both arrays, z-dim) ----------------
__global__ void __launch_bounds__(256)
transpose_kernel(const int* __restrict__ act, const float* __restrict__ rew) {
    __shared__ unsigned tile[32][33];
    const int tt = blockIdx.x * 32;   // t tile
    const int tb = blockIdx.y * 32;   // b tile
    const unsigned* src = (blockIdx.z == 0) ? (const unsigned*)act : (const unsigned*)rew;
    unsigned*       dst = (blockIdx.z == 0) ? (unsigned*)g_act_t  : (unsigned*)g_rew_t;
    const int tx = threadIdx.x, ty = threadIdx.y;
    #pragma unroll
    for (int i = 0; i < 32; i += 8)
        tile[ty + i][tx] = src[(long long)(tb + ty + i) * T_LEN + tt + tx];
    __syncthreads();
    #pragma unroll
    for (int i = 0; i < 32; i += 8)
        dst[(long long)(tt + ty + i) * B_SZ + tb + tx] = tile[tx][ty + i];
}

// ---------------- main recurrent kernel ----------------
// CTA = 128 threads = 4 warps = 2 element-groups of 32 elements.
//   warp 0: reward module, group 0     warp 1: action module, group 0
//   warp 2: reward module, group 1     warp 3: action module, group 1
// Each lane owns ONE batch element; its 32-dim module state lives in registers
// as 16 packed f32x2 pairs. Weights are read as warp-uniform SMEM broadcasts.
__global__ void __launch_bounds__(128)
memann_main(const float* __restrict__ w_r1, const float* __restrict__ b_r1,
            const float* __restrict__ w_r2, const float* __restrict__ b_r2,
            const float* __restrict__ w_a1, const float* __restrict__ b_a1,
            const float* __restrict__ w_a2, const float* __restrict__ b_a2,
            float*       __restrict__ out)
{
    __shared__ __align__(16) ull   wr1p[32][16];   // {w_r1[r][1+2p], w_r1[r][2+2p]}
    __shared__ __align__(16) ull   wa1p[32][16];   // {w_a1[r][4+2p], w_a1[r][5+2p]}
    __shared__ __align__(16) ull   wr2p[16];       // {w_r2[2p], w_r2[2p+1]}
    __shared__ __align__(16) ull   wa2p[4][16];    // {w_a2[k][2p], w_a2[k][2p+1]}
    __shared__ __align__(16) ull   biasp[32];      // {b_r1[r], 0}
    __shared__ __align__(16) ull   wc0p[32];       // {w_r1[r][0], 0}
    __shared__ __align__(16) float colb[32][4];    // w_a1[r][a] + b_a1[r]
    __shared__ __align__(16) float cbuf[2][2][32][4]; // [parity][group][lane][k]
    __shared__ float sc[5];                        // b_r2, b_a2[0..3]

    const int tid = threadIdx.x;

    // ---- one-time weight staging ----
    #pragma unroll
    for (int idx = tid; idx < 512; idx += 128) {
        int r = idx >> 4, p = idx & 15;
        wr1p[r][p] = pack2(w_r1[r * 33 + 1 + 2 * p], w_r1[r * 33 + 2 + 2 * p]);
        wa1p[r][p] = pack2(w_a1[r * 36 + 4 + 2 * p], w_a1[r * 36 + 5 + 2 * p]);
    }
    {
        int r = tid >> 2, a = tid & 3;
        colb[r][a] = w_a1[r * 36 + a] + b_a1[r];
    }
    if (tid < 32) {
        biasp[tid] = pack2(b_r1[tid], 0.0f);
        wc0p[tid]  = pack2(w_r1[tid * 33], 0.0f);
    }
    if (tid >= 32 && tid < 48) {
        int p = tid - 32;
        wr2p[p] = pack2(w_r2[2 * p], w_r2[2 * p + 1]);
    }
    if (tid >= 64 && tid < 128) {
        int k = (tid - 64) >> 4, p = (tid - 64) & 15;
        wa2p[k][p] = pack2(w_a2[k * 32 + 2 * p], w_a2[k * 32 + 2 * p + 1]);
    }
    if (tid == 48) sc[0] = b_r2[0];
    if (tid >= 49 && tid < 53) sc[tid - 48] = b_a2[tid - 49];
    __syncthreads();

    const int lane   = tid & 31;
    const int wid    = tid >> 5;
    const int gl     = wid >> 1;          // group within CTA (0/1)
    const int module = wid & 1;           // 0 = reward, 1 = action
    const long long b = (long long)(blockIdx.x * 2 + gl) * 32 + lane;
    const int*   ap = g_act_t + b;
    const float* rp = g_rew_t + b;

    if (module == 0) {
        // ================= reward module + q/output =================
        const float br2 = sc[0];
        float* op = out + b * (long long)(NSTEP * 4);
        ull srp[16];
        #pragma unroll
        for (int p = 0; p < 16; p++) srp[p] = 0ull;
        float q0 = 0.f, q1 = 0.f, q2 = 0.f, q3 = 0.f;
        int   a_cur = ap[0];
        float r_cur = rp[0];

        for (int t = 0; t < NSTEP; t++) {
            const int   a_nxt = ap[(t + 1) * B_SZ];
            const float r_nxt = rp[(t + 1) * B_SZ];
            const ull rdup = pack2(r_cur, r_cur);

            float sn[32];
            #pragma unroll
            for (int r4 = 0; r4 < 32; r4 += 4) {
                ull acc[4];
                #pragma unroll
                for (int m = 0; m < 4; m++) {
                    acc[m] = biasp[r4 + m];
                    ffma2(acc[m], wc0p[r4 + m], rdup);
                }
                #pragma unroll
                for (int p2 = 0; p2 < 8; p2++) {
                    #pragma unroll
                    for (int m = 0; m < 4; m++) {
                        ulonglong2 w = *(const ulonglong2*)&wr1p[r4 + m][p2 * 2];
                        ffma2(acc[m], w.x, srp[2 * p2]);
                        ffma2(acc[m], w.y, srp[2 * p2 + 1]);
                    }
                }
                #pragma unroll
                for (int m = 0; m < 4; m++) {
                    float2 u = unpack2(acc[m]);
                    sn[r4 + m] = tanh_fast(u.x + u.y);
                }
            }
            #pragma unroll
            for (int p = 0; p < 16; p++) srp[p] = pack2(sn[2 * p], sn[2 * p + 1]);

            // q_new = w_r2 . sr_t + b_r2 (fully in-lane)
            ull qa = 0ull;
            #pragma unroll
            for (int p2 = 0; p2 < 8; p2++) {
                ulonglong2 w = *(const ulonglong2*)&wr2p[p2 * 2];
                ffma2(qa, w.x, srp[2 * p2]);
                ffma2(qa, w.y, srp[2 * p2 + 1]);
            }
            float2 qf = unpack2(qa);
            const float q_new = qf.x + qf.y + br2;

            q0 = (a_cur == 0) ? q_new : q0 * 0.95f;
            q1 = (a_cur == 1) ? q_new : q1 * 0.95f;
            q2 = (a_cur == 2) ? q_new : q2 * 0.95f;
            q3 = (a_cur == 3) ? q_new : q3 * 0.95f;

            __syncthreads();   // action warp has published c_t for step t

            float4 c = *(const float4*)&cbuf[t & 1][gl][lane][0];
            float4 o = make_float4(q0 + c.x, q1 + c.y, q2 + c.z, q3 + c.w);
            *(float4*)(op + t * 4) = o;

            a_cur = a_nxt; r_cur = r_nxt;
        }
    } else {
        // ================= action-history module + c_t =================
        const float ba0 = sc[1], ba1 = sc[2], ba2v = sc[3], ba3 = sc[4];
        ull sap[16];
        #pragma unroll
        for (int p = 0; p < 16; p++) sap[p] = 0ull;
        int a_cur = ap[0];

        for (int t = 0; t < NSTEP; t++) {
            const int a_nxt = ap[(t + 1) * B_SZ];

            float sn[32];
            #pragma unroll
            for (int r4 = 0; r4 < 32; r4 += 4) {
                ull acc[4];
                #pragma unroll
                for (int m = 0; m < 4; m++) acc[m] = 0ull;
                #pragma unroll
                for (int p2 = 0; p2 < 8; p2++) {
                    #pragma unroll
                    for (int m = 0; m < 4; m++) {
                        ulonglong2 w = *(const ulonglong2*)&wa1p[r4 + m][p2 * 2];
                        ffma2(acc[m], w.x, sap[2 * p2]);
                        ffma2(acc[m], w.y, sap[2 * p2 + 1]);
                    }
                }
                #pragma unroll
                for (int m = 0; m < 4; m++) {
                    float2 u = unpack2(acc[m]);
                    sn[r4 + m] = tanh_fast(u.x + u.y + colb[r4 + m][a_cur]);
                }
            }
            #pragma unroll
            for (int p = 0; p < 16; p++) sap[p] = pack2(sn[2 * p], sn[2 * p + 1]);

            // c_t = W_a2 @ sa_t + b_a2 (fully in-lane, 4 outputs)
            ull c0 = 0ull, c1 = 0ull, c2 = 0ull, c3 = 0ull;
            #pragma unroll
            for (int p2 = 0; p2 < 8; p2++) {
                ulonglong2 w0 = *(const ulonglong2*)&wa2p[0][p2 * 2];
                ulonglong2 w1 = *(const ulonglong2*)&wa2p[1][p2 * 2];
                ulonglong2 w2 = *(const ulonglong2*)&wa2p[2][p2 * 2];
                ulonglong2 w3 = *(const ulonglong2*)&wa2p[3][p2 * 2];
                ffma2(c0, w0.x, sap[2 * p2]); ffma2(c0, w0.y, sap[2 * p2 + 1]);
                ffma2(c1, w1.x, sap[2 * p2]); ffma2(c1, w1.y, sap[2 * p2 + 1]);
                ffma2(c2, w2.x, sap[2 * p2]); ffma2(c2, w2.y, sap[2 * p2 + 1]);
                ffma2(c3, w3.x, sap[2 * p2]); ffma2(c3, w3.y, sap[2 * p2 + 1]);
            }
            float2 f0 = unpack2(c0), f1 = unpack2(c1), f2 = unpack2(c2), f3 = unpack2(c3);
            float4 cv = make_float4(f0.x + f0.y + ba0, f1.x + f1.y + ba1,
                                    f2.x + f2.y + ba2v, f3.x + f3.y + ba3);
            *(float4*)&cbuf[t & 1][gl][lane][0] = cv;

            __syncthreads();   // matches reward warp's barrier for step t

            a_cur = a_nxt;
        }
    }
}

extern "C" void kernel_launch(void* const* d_in, const int* in_sizes, int n_in,
                              void* d_out, int out_size) {
    (void)in_sizes; (void)n_in; (void)out_size;
    transpose_kernel<<<dim3(T_LEN / 32, B_SZ / 32, 2), dim3(32, 8)>>>(
        (const int*)d_in[0], (const float*)d_in[1]);
    memann_main<<<B_SZ / 64, 128>>>(
        (const float*)d_in[2], (const float*)d_in[3],   // w_r1, b_r1
        (const float*)d_in[4], (const float*)d_in[5],   // w_r2, b_r2
        (const float*)d_in[6], (const float*)d_in[7],   // w_a1, b_a1
        (const float*)d_in[8], (const float*)d_in[9],   // w_a2, b_a2
        (float*)d_out);
}

// round 3
// speedup vs baseline: 2.7182x; 2.7182x over previous
#include <cuda_runtime.h>

#define T_LEN  1024
#define NSTEP  1023
#define B_SZ   8192

typedef unsigned long long ull;

// scratch: time-major inputs + c_t buffer
__device__ int   g_act_t[T_LEN * B_SZ];                 // [t][b]
__device__ float g_rew_t[T_LEN * B_SZ];                 // [t][b]
__device__ float g_c[(size_t)B_SZ * NSTEP * 4];         // [b][t][4]

// ---------------- helpers ----------------
__device__ __forceinline__ void ffma2(ull& d, ull a, ull b) {
    asm("fma.rn.f32x2 %0, %1, %2, %0;" : "+l"(d) : "l"(a), "l"(b));
}
__device__ __forceinline__ ull pack2(float x, float y) {
    ull r; asm("mov.b64 %0, {%1, %2};" : "=l"(r) : "f"(x), "f"(y)); return r;
}
__device__ __forceinline__ float2 unpack2(ull v) {
    float2 r; asm("mov.b64 {%0, %1}, %2;" : "=f"(r.x), "=f"(r.y) : "l"(v)); return r;
}
__device__ __forceinline__ float tanh_fast(float x) {   // ~1e-6 abs err
    float e, r;
    asm("ex2.approx.f32 %0, %1;" : "=f"(e) : "f"(x * 2.8853900817779268f));
    asm("rcp.approx.f32 %0, %1;" : "=f"(r) : "f"(e + 1.0f));
    return fmaf(-2.0f, r, 1.0f);
}

// ---------------- transpose [B][T] -> [T][B] ----------------
__global__ void __launch_bounds__(256)
transpose_kernel(const int* __restrict__ act, const float* __restrict__ rew) {
    __shared__ unsigned tile[32][33];
    const int tt = blockIdx.x * 32, tb = blockIdx.y * 32;
    const unsigned* src = (blockIdx.z == 0) ? (const unsigned*)act : (const unsigned*)rew;
    unsigned*       dst = (blockIdx.z == 0) ? (unsigned*)g_act_t  : (unsigned*)g_rew_t;
    const int tx = threadIdx.x, ty = threadIdx.y;
    #pragma unroll
    for (int i = 0; i < 32; i += 8)
        tile[ty + i][tx] = src[(long long)(tb + ty + i) * T_LEN + tt + tx];
    __syncthreads();
    #pragma unroll
    for (int i = 0; i < 32; i += 8)
        dst[(long long)(tt + ty + i) * B_SZ + tb + tx] = tile[tx][ty + i];
}

// ---------------- main recurrent kernel ----------------
// grid = 128 CTAs x 256 thr (8 warps). CTAs 0..63: reward module; 64..127: action.
// Warp handles 16 elements; lane pair (2e, 2e+1) shares element e: lane h owns
// weight rows / state dims [16h, 16h+16) in registers; halves swap via SHFL.
__global__ void __launch_bounds__(256, 1)
memann_mod(const float* __restrict__ w_r1, const float* __restrict__ b_r1,
           const float* __restrict__ w_r2, const float* __restrict__ b_r2,
           const float* __restrict__ w_a1, const float* __restrict__ b_a1,
           const float* __restrict__ w_a2, const float* __restrict__ b_a2,
           float*       __restrict__ out)
{
    // weight SMEM, interleaved so the 2 per-warp addresses are 16B apart
    __shared__ __align__(16) ulonglong2 wrk[16][8][2];  // [m][pp][h]: row h*16+m, x-pairs 2pp,2pp+1
    __shared__ __align__(16) ulonglong2 wak[16][8][2];
    __shared__ __align__(16) ulonglong2 binit[16][2];   // {pack2(b_r1,0), pack2(w_r1[.,0],0)}
    __shared__ __align__(16) ull  wr2s[2][8];
    __shared__ __align__(16) ull  wa2s[4][2][8];
    __shared__ __align__(16) float colbf[4][2][16];     // w_a1[r][a]+b_a1[r]
    __shared__ float sc[5];                              // b_r2, b_a2[0..3]

    const int tid = threadIdx.x;
    const bool is_reward = blockIdx.x < 64;

    // ---- staging ----
    if (is_reward) {
        #pragma unroll
        for (int k = 0; k < 2; k++) {
            int idx = tid * 2 + k;                 // 512 ull
            int u2 = idx & 1, h = (idx >> 1) & 1, pp = (idx >> 2) & 7, m = idx >> 5;
            int row = h * 16 + m, u = 2 * pp + u2;
            ((ull*)&wrk[m][pp][h])[u2] =
                pack2(w_r1[row * 33 + 1 + 2 * u], w_r1[row * 33 + 2 + 2 * u]);
        }
        if (tid < 64) {
            int u2 = tid & 1, h = (tid >> 1) & 1, m = tid >> 2;
            int row = h * 16 + m;
            ((ull*)&binit[m][h])[u2] = u2 ? pack2(w_r1[row * 33], 0.f)
                                          : pack2(b_r1[row], 0.f);
        }
        if (tid >= 64 && tid < 80) {
            int h = (tid - 64) >> 3, pp = (tid - 64) & 7;
            wr2s[h][pp] = pack2(w_r2[16 * h + 2 * pp], w_r2[16 * h + 2 * pp + 1]);
        }
        if (tid == 80) sc[0] = b_r2[0];
    } else {
        #pragma unroll
        for (int k = 0; k < 2; k++) {
            int idx = tid * 2 + k;
            int u2 = idx & 1, h = (idx >> 1) & 1, pp = (idx >> 2) & 7, m = idx >> 5;
            int row = h * 16 + m, u = 2 * pp + u2;
            ((ull*)&wak[m][pp][h])[u2] =
                pack2(w_a1[row * 36 + 4 + 2 * u], w_a1[row * 36 + 5 + 2 * u]);
        }
        if (tid < 128) {
            int a = tid >> 5, h = (tid >> 4) & 1, m = tid & 15;
            int row = h * 16 + m;
            colbf[a][h][m] = w_a1[row * 36 + a] + b_a1[row];
        }
        if (tid >= 128 && tid < 192) {
            int k2 = (tid - 128) >> 4, h = (tid - 128 >> 3) & 1, pp = (tid - 128) & 7;
            wa2s[k2][h][pp] = pack2(w_a2[k2 * 32 + 16 * h + 2 * pp],
                                    w_a2[k2 * 32 + 16 * h + 2 * pp + 1]);
        }
        if (tid >= 192 && tid < 196) sc[1 + tid - 192] = b_a2[tid - 192];
    }
    __syncthreads();

    const int lane = tid & 31, wid = tid >> 5;
    const int h  = lane & 1;
    const int el = lane >> 1;
    const int cta_mod = is_reward ? blockIdx.x : blockIdx.x - 64;
    const long long b = (long long)cta_mod * 128 + wid * 16 + el;
    const int*   ap = g_act_t + b;
    const float* rp = g_rew_t + b;

    ull sh[8];
    #pragma unroll
    for (int u = 0; u < 8; u++) sh[u] = 0ull;

    if (is_reward) {
        // hoist row constants + w_r2 half into registers
        ulonglong2 bi[16];
        #pragma unroll
        for (int m = 0; m < 16; m++) bi[m] = binit[m][h];
        ull w2r[8];
        #pragma unroll
        for (int pp = 0; pp < 8; pp++) w2r[pp] = wr2s[h][pp];
        const float br2 = sc[0];
        const int   kA = 2 * h, kB = 2 * h + 1;
        float qA = 0.f, qB = 0.f;
        float* op = out + (b * NSTEP) * 4 + 2 * h;

        int   a_cur = ap[0];
        float r_cur = rp[0];
        for (int t = 0; t < NSTEP; t++) {
            const int   a_nxt = ap[(t + 1) * B_SZ];
            const float r_nxt = rp[(t + 1) * B_SZ];
            ull xo[8];
            #pragma unroll
            for (int u = 0; u < 8; u++) xo[u] = __shfl_xor_sync(0xFFFFFFFFu, sh[u], 1);
            const ull rdup = pack2(r_cur, r_cur);

            float sn[16];
            #pragma unroll
            for (int m4 = 0; m4 < 4; m4++) {
                ull acc[4];
                #pragma unroll
                for (int mm = 0; mm < 4; mm++) {
                    ulonglong2 iv = bi[m4 * 4 + mm];
                    acc[mm] = iv.x;
                    ffma2(acc[mm], iv.y, rdup);
                }
                #pragma unroll
                for (int ppo = 0; ppo < 4; ppo++) {      // own half first
                    const int pp = h * 4 + ppo;
                    #pragma unroll
                    for (int mm = 0; mm < 4; mm++) {
                        ulonglong2 w = wrk[m4 * 4 + mm][pp][h];
                        ffma2(acc[mm], w.x, sh[2 * ppo]);
                        ffma2(acc[mm], w.y, sh[2 * ppo + 1]);
                    }
                }
                #pragma unroll
                for (int ppo = 0; ppo < 4; ppo++) {      // partner half
                    const int pq = (1 - h) * 4 + ppo;
                    #pragma unroll
                    for (int mm = 0; mm < 4; mm++) {
                        ulonglong2 w = wrk[m4 * 4 + mm][pq][h];
                        ffma2(acc[mm], w.x, xo[2 * ppo]);
                        ffma2(acc[mm], w.y, xo[2 * ppo + 1]);
                    }
                }
                #pragma unroll
                for (int mm = 0; mm < 4; mm++) {
                    float2 u = unpack2(acc[mm]);
                    sn[m4 * 4 + mm] = tanh_fast(u.x + u.y);
                }
            }
            #pragma unroll
            for (int u = 0; u < 8; u++) sh[u] = pack2(sn[2 * u], sn[2 * u + 1]);

            ull qa = 0ull;
            #pragma unroll
            for (int pp = 0; pp < 8; pp++) ffma2(qa, w2r[pp], sh[pp]);
            float2 qf = unpack2(qa);
            float qs = qf.x + qf.y;
            qs += __shfl_xor_sync(0xFFFFFFFFu, qs, 1);
            const float q_new = qs + br2;

            qA = (a_cur == kA) ? q_new : qA * 0.95f;
            qB = (a_cur == kB) ? q_new : qB * 0.95f;
            *(float2*)(op + (size_t)t * 4) = make_float2(qA, qB);

            a_cur = a_nxt; r_cur = r_nxt;
        }
    } else {
        ull w2a[4][8];
        #pragma unroll
        for (int k = 0; k < 4; k++)
            #pragma unroll
            for (int pp = 0; pp < 8; pp++) w2a[k][pp] = wa2s[k][h][pp];
        const float baA = h ? sc[3] : sc[1];
        const float baB = h ? sc[4] : sc[2];
        float* cp = g_c + (b * NSTEP) * 4 + 2 * h;

        int a_cur = ap[0];
        for (int t = 0; t < NSTEP; t++) {
            const int a_nxt = ap[(t + 1) * B_SZ];
            ull xo[8];
            #pragma unroll
            for (int u = 0; u < 8; u++) xo[u] = __shfl_xor_sync(0xFFFFFFFFu, sh[u], 1);

            float sn[16];
            #pragma unroll
            for (int m4 = 0; m4 < 4; m4++) {
                const float4 cb = *(const float4*)&colbf[a_cur][h][m4 * 4];
                ull acc[4];
                #pragma unroll
                for (int mm = 0; mm < 4; mm++) acc[mm] = 0ull;
                #pragma unroll
                for (int ppo = 0; ppo < 4; ppo++) {
                    const int pp = h * 4 + ppo;
                    #pragma unroll
                    for (int mm = 0; mm < 4; mm++) {
                        ulonglong2 w = wak[m4 * 4 + mm][pp][h];
                        ffma2(acc[mm], w.x, sh[2 * ppo]);
                        ffma2(acc[mm], w.y, sh[2 * ppo + 1]);
                    }
                }
                #pragma unroll
                for (int ppo = 0; ppo < 4; ppo++) {
                    const int pq = (1 - h) * 4 + ppo;
                    #pragma unroll
                    for (int mm = 0; mm < 4; mm++) {
                        ulonglong2 w = wak[m4 * 4 + mm][pq][h];
                        ffma2(acc[mm], w.x, xo[2 * ppo]);
                        ffma2(acc[mm], w.y, xo[2 * ppo + 1]);
                    }
                }
                const float cbv[4] = {cb.x, cb.y, cb.z, cb.w};
                #pragma unroll
                for (int mm = 0; mm < 4; mm++) {
                    float2 u = unpack2(acc[mm]);
                    sn[m4 * 4 + mm] = tanh_fast(u.x + u.y + cbv[mm]);
                }
            }
            #pragma unroll
            for (int u = 0; u < 8; u++) sh[u] = pack2(sn[2 * u], sn[2 * u + 1]);

            ull ca0 = 0ull, ca1 = 0ull, ca2 = 0ull, ca3 = 0ull;
            #pragma unroll
            for (int pp = 0; pp < 8; pp++) {
                ffma2(ca0, w2a[0][pp], sh[pp]);
                ffma2(ca1, w2a[1][pp], sh[pp]);
                ffma2(ca2, w2a[2][pp], sh[pp]);
                ffma2(ca3, w2a[3][pp], sh[pp]);
            }
            float2 f0 = unpack2(ca0), f1 = unpack2(ca1), f2 = unpack2(ca2), f3 = unpack2(ca3);
            float c0 = f0.x + f0.y, c1 = f1.x + f1.y, c2 = f2.x + f2.y, c3 = f3.x + f3.y;
            c0 += __shfl_xor_sync(0xFFFFFFFFu, c0, 1);
            c1 += __shfl_xor_sync(0xFFFFFFFFu, c1, 1);
            c2 += __shfl_xor_sync(0xFFFFFFFFu, c2, 1);
            c3 += __shfl_xor_sync(0xFFFFFFFFu, c3, 1);
            const float cA = (h ? c2 : c0) + baA;
            const float cB = (h ? c3 : c1) + baB;
            *(float2*)(cp + (size_t)t * 4) = make_float2(cA, cB);

            a_cur = a_nxt;
        }
    }
}

// ---------------- out += c ----------------
__global__ void __launch_bounds__(256)
add_kernel(float* __restrict__ out) {
    const size_t n4 = (size_t)B_SZ * NSTEP;        // float4 count
    float4* o = (float4*)out;
    const float4* c = (const float4*)g_c;
    for (size_t i = (size_t)blockIdx.x * 256 + threadIdx.x; i < n4;
         i += (size_t)gridDim.x * 256) {
        float4 a = o[i], b = c[i];
        a.x += b.x; a.y += b.y; a.z += b.z; a.w += b.w;
        o[i] = a;
    }
}

extern "C" void kernel_launch(void* const* d_in, const int* in_sizes, int n_in,
                              void* d_out, int out_size) {
    (void)in_sizes; (void)n_in; (void)out_size;
    transpose_kernel<<<dim3(T_LEN / 32, B_SZ / 32, 2), dim3(32, 8)>>>(
        (const int*)d_in[0], (const float*)d_in[1]);
    memann_mod<<<128, 256>>>(
        (const float*)d_in[2], (const float*)d_in[3],
        (const float*)d_in[4], (const float*)d_in[5],
        (const float*)d_in[6], (const float*)d_in[7],
        (const float*)d_in[8], (const float*)d_in[9],
        (float*)d_out);
    add_kernel<<<2048, 256>>>((float*)d_out);
}